// round 1
// baseline (speedup 1.0000x reference)
#include <cuda_runtime.h>
#include <cuda_bf16.h>

#define PI_D 3.14159265358979323846
#define DNUM 729
#define ANUM 180
#define HNUM 512
#define WNUM 512
#define NPIX (HNUM * WNUM)
#define BNUM 2

// ---------------- device scratch (no allocations allowed) ----------------
__device__ float g_h[DNUM];                 // real spatial filter h[d]
__device__ float g_cos[ANUM];
__device__ float g_sin[ANUM];
__device__ float g_filt[BNUM * ANUM * DNUM]; // filtered sinograms
__device__ unsigned int g_max_bits;          // order-preserving float-max key

// ---------------- kernel 1: init filter h, cos/sin tables, reset max ------
// grid <<<729, 32>>> : one block (one warp) per filter tap j.
__global__ void fbp_init_kernel() {
    int j = blockIdx.x;
    int l = threadIdx.x;
    if (j == 0 && l == 0) g_max_bits = 0u;   // key(-inf) > 0, so 0 is safe floor
    if (j < ANUM && l == 0) {
        double ang = (double)j * (PI_D / 179.0);
        g_cos[j] = (float)cos(ang);
        g_sin[j] = (float)sin(ang);
    }
    // h[j] = (1/729) * (0.25 - (1/pi^2) * sum_{odd k} cos(2*pi*k*j/729)/k^2)
    const float C2 = (float)(2.0 * PI_D / 729.0);
    const float NI = (float)(-1.0 / (PI_D * PI_D));
    float acc = 0.0f;
    for (int k = 1 + 2 * l; k < DNUM; k += 64) {
        int r = (k * j) % DNUM;                   // exact arg reduction
        float coef = NI / ((float)k * (float)k);
        acc += coef * cosf((float)r * C2);
    }
    #pragma unroll
    for (int o = 16; o; o >>= 1) acc += __shfl_xor_sync(0xffffffffu, acc, o);
    if (l == 0) g_h[j] = (0.25f + acc) * (1.0f / 729.0f);
}

// ---------------- kernel 2: circular convolution filtering ---------------
// grid <<<B*A, 256>>> : one block per sinogram row.
__global__ void fbp_filter_kernel(const float* __restrict__ sino) {
    __shared__ float s_s[DNUM];
    __shared__ float s_hx[2 * DNUM - 1];   // unwrapped: s_hx[i] = h[(i+1) mod 729]
    int tid = threadIdx.x;
    int row = blockIdx.x;
    const float* sr = sino + row * DNUM;
    for (int i = tid; i < DNUM; i += 256) s_s[i] = sr[i];
    for (int i = tid; i < 2 * DNUM - 1; i += 256) {
        int jj = i + 1;
        if (jj >= DNUM) jj -= DNUM;
        s_hx[i] = g_h[jj];
    }
    __syncthreads();

    int n0 = tid, n1 = tid + 256, n2 = tid + 512;
    const float* h0 = s_hx + n0 + (DNUM - 1);
    const float* h1 = s_hx + n1 + (DNUM - 1);
    const float* h2 = s_hx + ((n2 < DNUM ? n2 : 0) + (DNUM - 1));
    float a0 = 0.f, a1 = 0.f, a2 = 0.f;
    #pragma unroll 9
    for (int m = 0; m < DNUM; m++) {
        float sv = s_s[m];
        a0 = fmaf(sv, h0[-m], a0);
        a1 = fmaf(sv, h1[-m], a1);
        a2 = fmaf(sv, h2[-m], a2);
    }
    float* fo = g_filt + row * DNUM;
    fo[n0] = a0;
    fo[n1] = a1;
    if (n2 < DNUM) fo[n2] = a2;
}

// ---------------- kernel 3: backprojection + max reduction ---------------
// grid <<<B*1024, 256>>> : one thread per pixel.
__global__ void fbp_backproject_kernel(float* __restrict__ out) {
    __shared__ float sc[ANUM], ss[ANUM];
    __shared__ float red[8];
    int tid = threadIdx.x;
    if (tid < ANUM) { sc[tid] = g_cos[tid]; ss[tid] = g_sin[tid]; }
    __syncthreads();

    int blk = blockIdx.x;
    int b = blk >> 10;
    int p = ((blk & 1023) << 8) | tid;
    int y = p >> 9;
    int x = p & 511;
    float xc = (float)x - 256.0f;   // W/2
    float yc = (float)y - 256.0f;   // H/2
    const float* fb = g_filt + b * (ANUM * DNUM);
    const float K = (float)(729.0 / (2.0 * PI_D));

    float acc = 0.0f;
    #pragma unroll 4
    for (int a = 0; a < ANUM; a++) {
        float rot = fmaf(xc, sc[a], yc * ss[a]);
        float t = fminf(fmaxf(rot * K, 0.0f), 728.0f);
        int i = (int)t;                     // truncation == ref int32 cast
        acc += __ldg(fb + a * DNUM + i);
    }
    float v = acc * (float)(PI_D / 180.0);
    out[b * NPIX + p] = v;

    // block max -> global atomic (order-preserving uint encoding)
    float m = v;
    #pragma unroll
    for (int o = 16; o; o >>= 1) m = fmaxf(m, __shfl_xor_sync(0xffffffffu, m, o));
    if ((tid & 31) == 0) red[tid >> 5] = m;
    __syncthreads();
    if (tid == 0) {
        #pragma unroll
        for (int w = 1; w < 8; w++) m = fmaxf(m, red[w]);
        unsigned u = __float_as_uint(m);
        unsigned key = (u & 0x80000000u) ? ~u : (u | 0x80000000u);
        atomicMax(&g_max_bits, key);
    }
}

// ---------------- kernel 4: clip to [0, max] ------------------------------
__global__ void fbp_clip_kernel(float* __restrict__ out) {
    int idx = blockIdx.x * 256 + threadIdx.x;
    unsigned key = g_max_bits;
    unsigned u = (key & 0x80000000u) ? (key ^ 0x80000000u) : ~key;
    float M = __uint_as_float(u);
    float v = out[idx];
    out[idx] = fminf(fmaxf(v, 0.0f), M);
}

// --------------------------------------------------------------------------
extern "C" void kernel_launch(void* const* d_in, const int* in_sizes, int n_in,
                              void* d_out, int out_size) {
    (void)in_sizes; (void)n_in; (void)out_size;
    const float* sino = (const float*)d_in[0];
    float* out = (float*)d_out;

    fbp_init_kernel<<<DNUM, 32>>>();
    fbp_filter_kernel<<<BNUM * ANUM, 256>>>(sino);
    fbp_backproject_kernel<<<BNUM * 1024, 256>>>(out);
    fbp_clip_kernel<<<(BNUM * NPIX) / 256, 256>>>(out);
}

// round 2
// speedup vs baseline: 1.7722x; 1.7722x over previous
#include <cuda_runtime.h>
#include <cuda_bf16.h>

#define PI_D 3.14159265358979323846
#define DNUM 729
#define DPAD 732            /* g_filt row stride (16B aligned) */
#define ANUM 180
#define HNUM 512
#define WNUM 512
#define NPIX (HNUM * WNUM)
#define BNUM 2

// ---------------- device scratch ----------------
__device__ float g_h[DNUM];
__device__ float g_cos[ANUM];
__device__ float g_sin[ANUM];
__device__ float g_filt[BNUM * ANUM * DPAD];
__device__ float g_pre0[BNUM][ANUM];    // S0[a]   = sum_{a'<a} f[b][a'][0],   a in [0,179]
__device__ float g_pre728[BNUM][ANUM];  // S728[a] = sum_{a'<a} f[b][a'][728]
__device__ unsigned int g_max_bits;

// ---------------- kernel 1: init h, cos/sin, reset max ----------------
__global__ void fbp_init_kernel() {
    int j = blockIdx.x;
    int l = threadIdx.x;
    if (j == 0 && l == 0) g_max_bits = 0u;
    if (j < ANUM && l == 0) {
        double ang = (double)j * (PI_D / 179.0);
        g_cos[j] = (float)cos(ang);
        g_sin[j] = (float)sin(ang);
    }
    const float C2 = (float)(2.0 * PI_D / 729.0);
    const float NI = (float)(-1.0 / (PI_D * PI_D));
    float acc = 0.0f;
    for (int k = 1 + 2 * l; k < DNUM; k += 64) {
        int r = (k * j) % DNUM;
        float coef = NI / ((float)k * (float)k);
        acc += coef * cosf((float)r * C2);
    }
    #pragma unroll
    for (int o = 16; o; o >>= 1) acc += __shfl_xor_sync(0xffffffffu, acc, o);
    if (l == 0) g_h[j] = (0.25f + acc) * (1.0f / 729.0f);
}

// ---------------- kernel 2: circular convolution, 4 outputs/thread -------
// grid <<<B*A, 192>>> : one block per sinogram row.
__global__ void fbp_filter_kernel(const float* __restrict__ sino) {
    __shared__ __align__(16) float s_s[736];     // s padded with zeros
    __shared__ __align__(16) float s_h[1464];    // huz[j] = h[(j-732) mod 729]
    int tid = threadIdx.x;
    int row = blockIdx.x;
    const float* sr = sino + row * DNUM;
    for (int i = tid; i < 736; i += 192) s_s[i] = (i < DNUM) ? sr[i] : 0.0f;
    for (int i = tid; i < 1464; i += 192) {
        int j = i - 3;                   // (i - 732) mod 729 == (i - 3) mod 729
        if (j < 0) j += 729;
        if (j >= 729) j -= 729;
        if (j >= 729) j -= 729;
        s_h[i] = g_h[j];
    }
    __syncthreads();

    if (tid < 183) {
        int n0 = 4 * tid;
        float a0 = 0.f, a1 = 0.f, a2 = 0.f, a3 = 0.f;
        const float4* sv4 = reinterpret_cast<const float4*>(s_s);
        #pragma unroll 3
        for (int g = 0; g < 183; ++g) {
            float4 sv = sv4[g];
            int base = n0 - 4 * g + 728;     // multiple of 4
            float4 hA = *reinterpret_cast<const float4*>(s_h + base);      // w0..w3
            float4 hB = *reinterpret_cast<const float4*>(s_h + base + 4);  // w4..w7
            // acc[dn] += s[dm] * w[4 + dn - dm]
            a0 = fmaf(sv.x, hB.x, a0); a0 = fmaf(sv.y, hA.w, a0);
            a0 = fmaf(sv.z, hA.z, a0); a0 = fmaf(sv.w, hA.y, a0);
            a1 = fmaf(sv.x, hB.y, a1); a1 = fmaf(sv.y, hB.x, a1);
            a1 = fmaf(sv.z, hA.w, a1); a1 = fmaf(sv.w, hA.z, a1);
            a2 = fmaf(sv.x, hB.z, a2); a2 = fmaf(sv.y, hB.y, a2);
            a2 = fmaf(sv.z, hB.x, a2); a2 = fmaf(sv.w, hA.w, a2);
            a3 = fmaf(sv.x, hB.w, a3); a3 = fmaf(sv.y, hB.z, a3);
            a3 = fmaf(sv.z, hB.y, a3); a3 = fmaf(sv.w, hB.x, a3);
        }
        float4* fo = reinterpret_cast<float4*>(g_filt + row * DPAD + n0);
        *fo = make_float4(a0, a1, a2, a3);
    }
}

// ---------------- kernel 3: prefix sums of f[.][a][0] and f[.][a][728] ---
// <<<1, 128>>> : one warp per (batch, column) pair.
__global__ void fbp_prefix_kernel() {
    int w = threadIdx.x >> 5;        // 0..3
    int l = threadIdx.x & 31;
    int b = w >> 1;
    int col = (w & 1) ? 728 : 0;
    const float* base = g_filt + b * (ANUM * DPAD) + col;
    float* outp = (w & 1) ? g_pre728[b] : g_pre0[b];
    float carry = 0.0f;
    #pragma unroll
    for (int c = 0; c < 6; ++c) {
        int a = c * 32 + l;
        float v = (a < 179) ? base[a * DPAD] : 0.0f;
        float s = v;
        #pragma unroll
        for (int off = 1; off < 32; off <<= 1) {
            float t = __shfl_up_sync(0xffffffffu, s, off);
            if (l >= off) s += t;
        }
        if (a < ANUM) outp[a] = carry + s - v;    // exclusive prefix
        carry += __shfl_sync(0xffffffffu, s, 31);
    }
}

// ---------------- kernel 4: backprojection via clamp intervals -----------
// grid <<<B*1024, 256>>> : one thread per pixel.
__global__ void fbp_backproject_kernel(float* __restrict__ out) {
    __shared__ float sc[ANUM], ss[ANUM], p0[ANUM], p728[ANUM];
    __shared__ float red[8];
    int tid = threadIdx.x;
    int blk = blockIdx.x;
    int b = blk >> 10;
    if (tid < ANUM) {
        sc[tid] = g_cos[tid];
        ss[tid] = g_sin[tid];
        p0[tid] = g_pre0[b][tid];
        p728[tid] = g_pre728[b][tid];
    }
    __syncthreads();

    int p = ((blk & 1023) << 8) | tid;
    int y = p >> 9;
    int x = p & 511;
    float xc = (float)x - 256.0f;
    float yc = (float)y - 256.0f;
    const float* fb = g_filt + b * (ANUM * DPAD);
    const float KIDX = (float)(729.0 / (2.0 * PI_D));
    const float STEPF = (float)(PI_D / 179.0);

    float R = sqrtf(xc * xc + yc * yc);
    // crossing position in angle-step units, in [0, 179)
    float acf = atan2f(-xc, yc) * (179.0f / (float)PI_D);
    if (acf < 0.0f) acf += 179.0f;
    if (acf >= 179.0f) acf -= 179.0f;

    int lo, hi;
    if (R < 16.0f) {            // fully exact over a in [0,178]
        lo = 0; hi = 178;
    } else {
        int half = 4 + (int)(asinf(6.2831853f / R) * (179.0f / (float)PI_D));
        lo = (int)ceilf(acf) - half;
        hi = (int)floorf(acf) + half;
    }

    float acc = 0.0f;
    for (int u = lo; u <= hi; ++u) {
        int a = u;
        if (a < 0) a += 179;
        else if (a > 178) a -= 179;
        float rot = fmaf(xc, sc[a], yc * ss[a]);
        float t = fminf(fmaxf(rot * KIDX, 0.0f), 728.0f);
        acc += __ldg(fb + a * DPAD + (int)t);
    }
    {   // angle 179 always exact (period-179 leftover)
        float rot = fmaf(xc, sc[179], yc * ss[179]);
        float t = fminf(fmaxf(rot * KIDX, 0.0f), 728.0f);
        acc += __ldg(fb + 179 * DPAD + (int)t);
    }

    // complement intervals (u-space complement [hi+1, lo+178])
    int i1lo = hi + 1, i1hi = min(178, lo + 178);   // direct: a = u, sign sR
    int i2lo = max(0, hi - 178), i2hi = lo - 1;     // shifted: a = u-179, sign -sR
    if (i1lo <= i1hi || i2lo <= i2hi) {
        float th = (acf + 89.0f) * STEPF;           // strictly inside (ac, ac+179)
        float s_c, s_n;
        __sincosf(th, &s_n, &s_c);
        float sR = xc * s_c + yc * s_n;             // sign of rot right of crossing
        bool pos = sR > 0.0f;
        if (i1lo <= i1hi)
            acc += pos ? (p728[i1hi + 1] - p728[i1lo]) : (p0[i1hi + 1] - p0[i1lo]);
        if (i2lo <= i2hi)
            acc += pos ? (p0[i2hi + 1] - p0[i2lo]) : (p728[i2hi + 1] - p728[i2lo]);
    }

    float v = acc * (float)(PI_D / 180.0);
    out[b * NPIX + p] = fmaxf(v, 0.0f);             // correct whenever global max >= 0

    // global max of raw v (for the all-negative fallback)
    float m = v;
    #pragma unroll
    for (int o = 16; o; o >>= 1) m = fmaxf(m, __shfl_xor_sync(0xffffffffu, m, o));
    if ((tid & 31) == 0) red[tid >> 5] = m;
    __syncthreads();
    if (tid == 0) {
        #pragma unroll
        for (int w = 1; w < 8; w++) m = fmaxf(m, red[w]);
        unsigned u = __float_as_uint(m);
        unsigned key = (u & 0x80000000u) ? ~u : (u | 0x80000000u);
        atomicMax(&g_max_bits, key);
    }
}

// ---------------- kernel 5: fallback fill when global max < 0 ------------
__global__ void fbp_clip_kernel(float* __restrict__ out) {
    unsigned key = g_max_bits;
    if (key & 0x80000000u) return;        // max >= 0: relu already correct
    float M = __uint_as_float(~key);      // max < 0: clip(v,0,M) == M everywhere
    for (int i = blockIdx.x * 256 + threadIdx.x; i < BNUM * NPIX; i += gridDim.x * 256)
        out[i] = M;
}

// --------------------------------------------------------------------------
extern "C" void kernel_launch(void* const* d_in, const int* in_sizes, int n_in,
                              void* d_out, int out_size) {
    (void)in_sizes; (void)n_in; (void)out_size;
    const float* sino = (const float*)d_in[0];
    float* out = (float*)d_out;

    fbp_init_kernel<<<DNUM, 32>>>();
    fbp_filter_kernel<<<BNUM * ANUM, 192>>>(sino);
    fbp_prefix_kernel<<<1, 128>>>();
    fbp_backproject_kernel<<<BNUM * 1024, 256>>>(out);
    fbp_clip_kernel<<<148, 256>>>(out);
}

// round 3
// speedup vs baseline: 1.8795x; 1.0605x over previous
#include <cuda_runtime.h>
#include <cuda_bf16.h>

#define PI_D 3.14159265358979323846
#define DNUM 729
#define DPAD 732
#define ANUM 180
#define HNUM 512
#define WNUM 512
#define NPIX (HNUM * WNUM)
#define BNUM 2
#define CHUNK 244

// ---------------- device scratch ----------------
__device__ float g_h[DNUM];
__device__ float g_cos[ANUM];
__device__ float g_sin[ANUM];
__device__ float g_filt[BNUM * ANUM * DPAD];
__device__ float g_pre0[BNUM][ANUM];
__device__ float g_pre728[BNUM][ANUM];
__device__ unsigned int g_max_bits;

// ---------------- f32x2 helpers ----------------
__device__ __forceinline__ unsigned long long dup2(float f) {
    unsigned long long r;
    asm("mov.b64 %0, {%1, %1};" : "=l"(r) : "f"(f));
    return r;
}
__device__ __forceinline__ void ffma2(unsigned long long& d,
                                      unsigned long long a,
                                      unsigned long long b) {
    asm("fma.rn.f32x2 %0, %1, %2, %0;" : "+l"(d) : "l"(a), "l"(b));
}
__device__ __forceinline__ void unpack2(unsigned long long v, float& lo, float& hi) {
    asm("mov.b64 {%0, %1}, %2;" : "=f"(lo), "=f"(hi) : "l"(v));
}

// ---------------- kernel 1: init h, cos/sin, reset max ----------------
__global__ void fbp_init_kernel() {
    int j = blockIdx.x;
    int l = threadIdx.x;
    if (j == 0 && l == 0) g_max_bits = 0u;
    if (j < ANUM && l == 0) {
        double ang = (double)j * (PI_D / 179.0);
        g_cos[j] = (float)cos(ang);
        g_sin[j] = (float)sin(ang);
    }
    const float C2 = (float)(2.0 * PI_D / 729.0);
    const float NI = (float)(-1.0 / (PI_D * PI_D));
    float acc = 0.0f;
    for (int k = 1 + 2 * l; k < DNUM; k += 64) {
        int r = (k * j) % DNUM;
        float coef = NI / ((float)k * (float)k);
        acc += coef * cosf((float)r * C2);
    }
    #pragma unroll
    for (int o = 16; o; o >>= 1) acc += __shfl_xor_sync(0xffffffffu, acc, o);
    if (l == 0) g_h[j] = (0.25f + acc) * (1.0f / 729.0f);
}

// ---------------- kernel 2: filter, f32x2-packed batch pair, 8x4 tiles ---
// grid <<<540, 64>>> : block = (angle a, n-chunk of 244); rows b=0 & b=1 packed.
__global__ void fbp_filter_kernel(const float* __restrict__ sino) {
    __shared__ __align__(16) float2 s2[736];   // (row_b0[m], row_b1[m]); zero-padded
    __shared__ __align__(16) float s_h[1472];  // s_h[i] = h[(i-735) mod 729]
    int tid = threadIdx.x;
    int blk = blockIdx.x;
    int a = blk / 3;
    int chunk = blk - 3 * a;
    const float* r0 = sino + a * DNUM;
    const float* r1 = sino + (ANUM + a) * DNUM;
    for (int i = tid; i < 736; i += 64) {
        float v0 = (i < DNUM) ? __ldg(r0 + i) : 0.0f;
        float v1 = (i < DNUM) ? __ldg(r1 + i) : 0.0f;
        s2[i] = make_float2(v0, v1);
    }
    for (int i = tid; i < 1472; i += 64) {
        int j = i - 6;                 // (i - 735) mod 729
        if (j < 0) j += 729;
        if (j >= 729) j -= 729;
        if (j >= 729) j -= 729;
        s_h[i] = g_h[j];
    }
    __syncthreads();

    if (tid < 61) {
        int n0 = chunk * CHUNK + 4 * tid;        // multiple of 4, <= 728
        unsigned long long ac0 = 0ull, ac1 = 0ull, ac2 = 0ull, ac3 = 0ull;
        const double* sd = reinterpret_cast<const double*>(s2);
        #pragma unroll 2
        for (int g = 0; g < 92; ++g) {
            int m0 = 8 * g;
            double2 sA = *reinterpret_cast<const double2*>(sd + m0);
            double2 sB = *reinterpret_cast<const double2*>(sd + m0 + 2);
            double2 sC = *reinterpret_cast<const double2*>(sd + m0 + 4);
            double2 sD = *reinterpret_cast<const double2*>(sd + m0 + 6);
            unsigned long long k0 = __double_as_longlong(sA.x);
            unsigned long long k1 = __double_as_longlong(sA.y);
            unsigned long long k2 = __double_as_longlong(sB.x);
            unsigned long long k3 = __double_as_longlong(sB.y);
            unsigned long long k4 = __double_as_longlong(sC.x);
            unsigned long long k5 = __double_as_longlong(sC.y);
            unsigned long long k6 = __double_as_longlong(sD.x);
            unsigned long long k7 = __double_as_longlong(sD.y);
            int L = n0 - m0 + 728;                // multiple of 4, in [0,1456]
            float4 h0 = *reinterpret_cast<const float4*>(s_h + L);
            float4 h1 = *reinterpret_cast<const float4*>(s_h + L + 4);
            float4 h2 = *reinterpret_cast<const float4*>(s_h + L + 8);
            unsigned long long H0 = dup2(h0.x), H1 = dup2(h0.y);
            unsigned long long H2 = dup2(h0.z), H3 = dup2(h0.w);
            unsigned long long H4 = dup2(h1.x), H5 = dup2(h1.y);
            unsigned long long H6 = dup2(h1.z), H7 = dup2(h1.w);
            unsigned long long H8 = dup2(h2.x), H9 = dup2(h2.y);
            unsigned long long H10 = dup2(h2.z);
            // acc[j] += s[k] * h[7 + j - k], k ascending (preserves m order)
            ffma2(ac0, k0, H7);  ffma2(ac1, k0, H8);  ffma2(ac2, k0, H9);  ffma2(ac3, k0, H10);
            ffma2(ac0, k1, H6);  ffma2(ac1, k1, H7);  ffma2(ac2, k1, H8);  ffma2(ac3, k1, H9);
            ffma2(ac0, k2, H5);  ffma2(ac1, k2, H6);  ffma2(ac2, k2, H7);  ffma2(ac3, k2, H8);
            ffma2(ac0, k3, H4);  ffma2(ac1, k3, H5);  ffma2(ac2, k3, H6);  ffma2(ac3, k3, H7);
            ffma2(ac0, k4, H3);  ffma2(ac1, k4, H4);  ffma2(ac2, k4, H5);  ffma2(ac3, k4, H6);
            ffma2(ac0, k5, H2);  ffma2(ac1, k5, H3);  ffma2(ac2, k5, H4);  ffma2(ac3, k5, H5);
            ffma2(ac0, k6, H1);  ffma2(ac1, k6, H2);  ffma2(ac2, k6, H3);  ffma2(ac3, k6, H4);
            ffma2(ac0, k7, H0);  ffma2(ac1, k7, H1);  ffma2(ac2, k7, H2);  ffma2(ac3, k7, H3);
        }
        float o00, o01, o02, o03, o10, o11, o12, o13;
        unpack2(ac0, o00, o10);
        unpack2(ac1, o01, o11);
        unpack2(ac2, o02, o12);
        unpack2(ac3, o03, o13);
        float4* f0 = reinterpret_cast<float4*>(g_filt + a * DPAD + n0);
        float4* f1 = reinterpret_cast<float4*>(g_filt + (ANUM + a) * DPAD + n0);
        *f0 = make_float4(o00, o01, o02, o03);
        *f1 = make_float4(o10, o11, o12, o13);
    }
}

// ---------------- kernel 3: prefix sums of cols 0 and 728 ---------------
__global__ void fbp_prefix_kernel() {
    int w = threadIdx.x >> 5;
    int l = threadIdx.x & 31;
    int b = w >> 1;
    int col = (w & 1) ? 728 : 0;
    const float* base = g_filt + b * (ANUM * DPAD) + col;
    float* outp = (w & 1) ? g_pre728[b] : g_pre0[b];
    float carry = 0.0f;
    #pragma unroll
    for (int c = 0; c < 6; ++c) {
        int a = c * 32 + l;
        float v = (a < 179) ? base[a * DPAD] : 0.0f;
        float s = v;
        #pragma unroll
        for (int off = 1; off < 32; off <<= 1) {
            float t = __shfl_up_sync(0xffffffffu, s, off);
            if (l >= off) s += t;
        }
        if (a < ANUM) outp[a] = carry + s - v;
        carry += __shfl_sync(0xffffffffu, s, 31);
    }
}

// ---------------- backprojection helpers --------------------------------
__device__ __forceinline__ float bp_one(const float* __restrict__ fb,
                                        const float* sKc, const float* sKs,
                                        float xc, float yc, int a) {
    float rs = fmaf(xc, sKc[a], yc * sKs[a]);
    float t = fminf(fmaxf(rs, 0.0f), 728.0f);
    return __ldg(fb + a * DPAD + (int)t);
}

__device__ __forceinline__ float run_sum(const float* __restrict__ fb,
                                         const float* sKc, const float* sKs,
                                         float xc, float yc, int a0, int a1) {
    float acc = 0.0f;
    int a = a0;
    #pragma unroll 1
    for (; a + 3 <= a1; a += 4) {
        float r0 = fmaf(xc, sKc[a    ], yc * sKs[a    ]);
        float r1 = fmaf(xc, sKc[a + 1], yc * sKs[a + 1]);
        float r2 = fmaf(xc, sKc[a + 2], yc * sKs[a + 2]);
        float r3 = fmaf(xc, sKc[a + 3], yc * sKs[a + 3]);
        r0 = fminf(fmaxf(r0, 0.0f), 728.0f);
        r1 = fminf(fmaxf(r1, 0.0f), 728.0f);
        r2 = fminf(fmaxf(r2, 0.0f), 728.0f);
        r3 = fminf(fmaxf(r3, 0.0f), 728.0f);
        float v0 = __ldg(fb + (a    ) * DPAD + (int)r0);
        float v1 = __ldg(fb + (a + 1) * DPAD + (int)r1);
        float v2 = __ldg(fb + (a + 2) * DPAD + (int)r2);
        float v3 = __ldg(fb + (a + 3) * DPAD + (int)r3);
        acc += (v0 + v1) + (v2 + v3);
    }
    #pragma unroll 1
    for (; a <= a1; ++a) acc += bp_one(fb, sKc, sKs, xc, yc, a);
    return acc;
}

// ---------------- kernel 4: backprojection via clamp intervals -----------
__global__ void fbp_backproject_kernel(float* __restrict__ out) {
    __shared__ float sKc[ANUM], sKs[ANUM], p0[ANUM], p728[ANUM];
    __shared__ float red[8];
    int tid = threadIdx.x;
    int blk = blockIdx.x;
    int b = blk >> 10;
    const float KIDX = (float)(729.0 / (2.0 * PI_D));
    if (tid < ANUM) {
        sKc[tid] = g_cos[tid] * KIDX;
        sKs[tid] = g_sin[tid] * KIDX;
        p0[tid] = g_pre0[b][tid];
        p728[tid] = g_pre728[b][tid];
    }
    __syncthreads();

    int p = ((blk & 1023) << 8) | tid;
    int y = p >> 9;
    int x = p & 511;
    float xc = (float)x - 256.0f;
    float yc = (float)y - 256.0f;
    const float* fb = g_filt + b * (ANUM * DPAD);

    float d2 = xc * xc + yc * yc;            // exact in fp32
    int lo, hi;
    float acfl = 0.0f;                       // floor(acf); unused for center
    if (d2 < 256.0f) {
        lo = 0; hi = 178;
    } else {
        int half = 5 + (int)(375.0f * rsqrtf(d2));   // superset of asin window
        float acf = atan2f(-xc, yc) * (179.0f / (float)PI_D);
        if (acf < 0.0f) acf += 179.0f;
        if (acf >= 179.0f) acf -= 179.0f;
        acfl = floorf(acf);
        lo = (int)ceilf(acf) - half;
        hi = (int)acfl + half;
    }

    float acc;
    if (lo < 0) {
        acc = run_sum(fb, sKc, sKs, xc, yc, lo + 179, 178)
            + run_sum(fb, sKc, sKs, xc, yc, 0, hi);
    } else if (hi > 178) {
        acc = run_sum(fb, sKc, sKs, xc, yc, lo, 178)
            + run_sum(fb, sKc, sKs, xc, yc, 0, hi - 179);
    } else {
        acc = run_sum(fb, sKc, sKs, xc, yc, lo, hi);
    }
    acc += bp_one(fb, sKc, sKs, xc, yc, 179);   // leftover angle, always exact

    // complement intervals (u-space complement [hi+1, lo+178])
    int i1lo = hi + 1, i1hi = min(178, lo + 178);
    int i2lo = max(0, hi - 178), i2hi = lo - 1;
    if (i1lo <= i1hi || i2lo <= i2hi) {
        int um = (int)acfl + 90;                 // strictly inside (acf, acf+179)
        float sR;
        if (um <= 178) {
            sR = fmaf(xc, sKc[um], yc * sKs[um]);
        } else {
            int am = um - 179;
            sR = -fmaf(xc, sKc[am], yc * sKs[am]);
        }
        bool pos = sR > 0.0f;
        if (i1lo <= i1hi)
            acc += pos ? (p728[i1hi + 1] - p728[i1lo]) : (p0[i1hi + 1] - p0[i1lo]);
        if (i2lo <= i2hi)
            acc += pos ? (p0[i2hi + 1] - p0[i2lo]) : (p728[i2hi + 1] - p728[i2lo]);
    }

    float v = acc * (float)(PI_D / 180.0);
    out[b * NPIX + p] = fmaxf(v, 0.0f);

    float m = v;
    #pragma unroll
    for (int o = 16; o; o >>= 1) m = fmaxf(m, __shfl_xor_sync(0xffffffffu, m, o));
    if ((tid & 31) == 0) red[tid >> 5] = m;
    __syncthreads();
    if (tid == 0) {
        #pragma unroll
        for (int w = 1; w < 8; w++) m = fmaxf(m, red[w]);
        unsigned u = __float_as_uint(m);
        unsigned key = (u & 0x80000000u) ? ~u : (u | 0x80000000u);
        atomicMax(&g_max_bits, key);
    }
}

// ---------------- kernel 5: fallback fill when global max < 0 ------------
__global__ void fbp_clip_kernel(float* __restrict__ out) {
    unsigned key = g_max_bits;
    if (key & 0x80000000u) return;
    float M = __uint_as_float(~key);
    for (int i = blockIdx.x * 256 + threadIdx.x; i < BNUM * NPIX; i += gridDim.x * 256)
        out[i] = M;
}

// --------------------------------------------------------------------------
extern "C" void kernel_launch(void* const* d_in, const int* in_sizes, int n_in,
                              void* d_out, int out_size) {
    (void)in_sizes; (void)n_in; (void)out_size;
    const float* sino = (const float*)d_in[0];
    float* out = (float*)d_out;

    fbp_init_kernel<<<DNUM, 32>>>();
    fbp_filter_kernel<<<540, 64>>>(sino);
    fbp_prefix_kernel<<<1, 128>>>();
    fbp_backproject_kernel<<<BNUM * 1024, 256>>>(out);
    fbp_clip_kernel<<<148, 256>>>(out);
}